// round 14
// baseline (speedup 1.0000x reference)
#include <cuda_runtime.h>

// Problem constants
#define TT    4096
#define FF    9
#define NSEQ  2048
#define L1    2049
#define L2    1025
#define L3    513

// Tiling: 9 tiles x 57 pooled outputs = 513 exactly
#define V3      57
#define NTILES  9
#define NUNITS  (NSEQ*NTILES)   // 18432 independent (seq,tile) work units
#define GRIDP   444             // 148 SMs x 3 CTAs, persistent
#define IN_LEN  470             // 8*57+14; reads up to h0[473] hit zero pad
#define NLOAD   (IN_LEN*FF)     // 4230
#define NPF     17              // ceil(4230/256)
#define IN_STR  476
#define S1_STR  236
#define S2_STR  124
#define W2_STR  49
#define W3_STR  97

#define NB_ITEMS 472            // 8 cog * 59 quads
#define NC_ITEMS 464            // 16 cog * 29 quads
#define ND_THREADS 240          // 16 co * 15 ug

#define OFF_S1   (9*IN_STR)
#define OFF_S2   (OFF_S1 + 16*S1_STR)
#define OFF_W1   (OFF_S2 + 32*S2_STR)
#define OFF_W2   (OFF_W1 + 432)
#define OFF_W3   (OFF_W2 + 32*W2_STR)
#define OFF_SB   (OFF_W3 + 16*W3_STR)
#define OFF_FACC (OFF_SB + 64)
#define SM_FLOATS (OFF_FACC + 256)
#define SMEM_BYTES (SM_FLOATS * 4)

__device__ float g_part[NUNITS * 16];   // per-(seq,tile) partial sums
__device__ float g_feat[NSEQ * 16];

__global__ __launch_bounds__(256, 3) void cnn_main(
    const float* __restrict__ x,
    const float* __restrict__ w1, const float* __restrict__ b1,
    const float* __restrict__ w2, const float* __restrict__ b2,
    const float* __restrict__ w3, const float* __restrict__ b3)
{
    extern __shared__ float sm[];
    float* h0  = sm;                  // [9][IN_STR]
    float* s1  = sm + OFF_S1;
    float* s2  = sm + OFF_S2;
    float* sw1 = sm + OFF_W1;
    float* sw2 = sm + OFF_W2;
    float* sw3 = sm + OFF_W3;
    float* sb  = sm + OFF_SB;
    float* facc= sm + OFF_FACC;

    const int tid = threadIdx.x;

    // per-thread (tl, ci) start for the strided load/store walk (stride 256 = 28*9+4)
    const int tl0 = tid / 9;
    const int ci0 = tid - 9 * tl0;

    // Zero all smem once: persistent zero padding.
    for (int i = tid; i < SM_FLOATS; i += 256) sm[i] = 0.f;
    __syncthreads();

    for (int i = tid; i < 16*27; i += 256) sw1[i] = w1[i];
    for (int i = tid; i < 32*48; i += 256) sw2[(i/48)*W2_STR + (i%48)] = w2[i];
    for (int i = tid; i < 16*96; i += 256) sw3[(i/96)*W3_STR + (i%96)] = w3[i];
    if (tid < 16)      sb[tid] = b1[tid];
    else if (tid < 48) sb[tid] = b2[tid-16];
    else if (tid < 64) sb[tid] = b3[tid-48];
    __syncthreads();

    float pf[NPF];

    // ---- prefetch for the first unit ----
    {
        int unit = blockIdx.x;
        int n    = unit / NTILES;
        int tile = unit - n * NTILES;
        const float* xin = x + (size_t)n * (TT * FF);
        const int tb = 8*(tile*V3) - 14;
        int tl = tl0, ci = ci0;
        #pragma unroll
        for (int it = 0; it < NPF; ++it) {
            int idx = tid + (it << 8);
            int t   = tb + tl;
            float v = 0.f;
            if (idx < NLOAD && (unsigned)t < (unsigned)TT) v = xin[t*FF + ci];
            pf[it] = v;
            ci += 4; tl += 28; if (ci >= 9) { ci -= 9; ++tl; }
        }
    }

    for (int unit = blockIdx.x; unit < NUNITS; unit += GRIDP) {
        const int n    = unit / NTILES;
        const int tile = unit - n * NTILES;
        const int va   = tile * V3;
        const int u1b  = 4*va - 6;
        const int u2b  = 2*va - 2;

        // ---- Phase A: store prefetched regs -> h0 (pure STS) ----
        {
            int tl = tl0, ci = ci0;
            #pragma unroll
            for (int it = 0; it < NPF; ++it) {
                int idx = tid + (it << 8);
                if (idx < NLOAD) h0[ci*IN_STR + tl] = pf[it];
                ci += 4; tl += 28; if (ci >= 9) { ci -= 9; ++tl; }
            }
        }
        __syncthreads();

        // ---- issue next unit's LDGs now; latency hidden by B/C/D ----
        if (unit + GRIDP < NUNITS) {
            int nu    = unit + GRIDP;
            int nn    = nu / NTILES;
            int ntile = nu - nn * NTILES;
            const float* xin = x + (size_t)nn * (TT * FF);
            const int tb = 8*(ntile*V3) - 14;
            int tl = tl0, ci = ci0;
            #pragma unroll
            for (int it = 0; it < NPF; ++it) {
                int idx = tid + (it << 8);
                int t   = tb + tl;
                float v = 0.f;
                if (idx < NLOAD && (unsigned)t < (unsigned)TT) v = xin[t*FF + ci];
                pf[it] = v;
                ci += 4; tl += 28; if (ci >= 9) { ci -= 9; ++tl; }
            }
        }

        // ---- Phase B: stage1 conv(9->16,k3,p2) + relu + pool2 ----
        #pragma unroll
        for (int it = 0; it < 2; ++it) {
            int item = tid + it*256;
            if (item < NB_ITEMS) {
                int cog = item & 7;
                int ug  = item >> 3;            // 0..58
                int co0 = cog * 2;
                int ul0 = ug * 4;
                float acc0[8], acc1[8];
                #pragma unroll
                for (int p = 0; p < 8; ++p) { acc0[p]=0.f; acc1[p]=0.f; }
                const float* wpa = sw1 + co0*27;
                const float* wpb = wpa + 27;
                const float* hp  = h0 + 2*ul0;
                #pragma unroll
                for (int ci = 0; ci < 9; ++ci) {
                    float in[10];
                    #pragma unroll
                    for (int j = 0; j < 10; ++j) in[j] = hp[j];
                    float wa0=wpa[0], wa1=wpa[1], wa2=wpa[2];
                    float wb0=wpb[0], wb1=wpb[1], wb2=wpb[2];
                    #pragma unroll
                    for (int p = 0; p < 8; ++p) {
                        acc0[p] += wa0*in[p] + wa1*in[p+1] + wa2*in[p+2];
                        acc1[p] += wb0*in[p] + wb1*in[p+1] + wb2*in[p+2];
                    }
                    wpa += 3; wpb += 3; hp += IN_STR;
                }
                float ba = sb[co0], bb = sb[co0+1];
                float4 r0, r1;
                float* pr0 = (float*)&r0;
                float* pr1 = (float*)&r1;
                #pragma unroll
                for (int u = 0; u < 4; ++u) {
                    int ug1 = u1b + ul0 + u;
                    bool valid = (ug1 >= 0) && (ug1 < L1);
                    float v0 = fmaxf(fmaxf(acc0[2*u]+ba, 0.f), fmaxf(acc0[2*u+1]+ba, 0.f));
                    float v1 = fmaxf(fmaxf(acc1[2*u]+bb, 0.f), fmaxf(acc1[2*u+1]+bb, 0.f));
                    pr0[u] = valid ? v0 : 0.f;
                    pr1[u] = valid ? v1 : 0.f;
                }
                *(float4*)(s1 +  co0   *S1_STR + ul0) = r0;
                *(float4*)(s1 + (co0+1)*S1_STR + ul0) = r1;
            }
        }
        __syncthreads();

        // ---- Phase C: stage2 conv(16->32,k3,p2) + relu + pool2 ----
        #pragma unroll
        for (int it = 0; it < 2; ++it) {
            int item = tid + it*256;
            if (item < NC_ITEMS) {
                int cog = item & 15;
                int ug  = item >> 4;            // 0..28
                int co0 = cog * 2;
                int ul0 = ug * 4;
                float acc0[8], acc1[8];
                #pragma unroll
                for (int p = 0; p < 8; ++p) { acc0[p]=0.f; acc1[p]=0.f; }
                const float* wpa = sw2 + co0*W2_STR;
                const float* wpb = wpa + W2_STR;
                const float* hp  = s1 + 2*ul0;
                #pragma unroll 4
                for (int ci = 0; ci < 16; ++ci) {
                    float in[10];
                    #pragma unroll
                    for (int j = 0; j < 10; ++j) in[j] = hp[j];
                    float wa0=wpa[0], wa1=wpa[1], wa2=wpa[2];
                    float wb0=wpb[0], wb1=wpb[1], wb2=wpb[2];
                    #pragma unroll
                    for (int p = 0; p < 8; ++p) {
                        acc0[p] += wa0*in[p] + wa1*in[p+1] + wa2*in[p+2];
                        acc1[p] += wb0*in[p] + wb1*in[p+1] + wb2*in[p+2];
                    }
                    wpa += 3; wpb += 3; hp += S1_STR;
                }
                float ba = sb[16+co0], bb = sb[16+co0+1];
                float4 r0, r1;
                float* pr0 = (float*)&r0;
                float* pr1 = (float*)&r1;
                #pragma unroll
                for (int u = 0; u < 4; ++u) {
                    int ug2 = u2b + ul0 + u;
                    bool valid = (ug2 >= 0) && (ug2 < L2);
                    float v0 = fmaxf(fmaxf(acc0[2*u]+ba, 0.f), fmaxf(acc0[2*u+1]+ba, 0.f));
                    float v1 = fmaxf(fmaxf(acc1[2*u]+bb, 0.f), fmaxf(acc1[2*u+1]+bb, 0.f));
                    pr0[u] = valid ? v0 : 0.f;
                    pr1[u] = valid ? v1 : 0.f;
                }
                *(float4*)(s2 +  co0   *S2_STR + ul0) = r0;
                *(float4*)(s2 + (co0+1)*S2_STR + ul0) = r1;
            }
        }
        __syncthreads();

        // ---- Phase D: stage3 conv(32->16,k3,p2) + relu + pool2 + partial sum ----
        if (tid < ND_THREADS) {
            int co  = tid & 15;
            int ug  = tid >> 4;             // 0..14
            int ul0 = ug * 4;
            float acc[8];
            #pragma unroll
            for (int p = 0; p < 8; ++p) acc[p] = 0.f;
            const float* wp = sw3 + co*W3_STR;
            const float* hp = s2 + 2*ul0;
            #pragma unroll 4
            for (int ci = 0; ci < 32; ++ci) {
                float in[10];
                #pragma unroll
                for (int j = 0; j < 10; ++j) in[j] = hp[j];
                float w0=wp[0], w1_=wp[1], w2_=wp[2];
                #pragma unroll
                for (int p = 0; p < 8; ++p)
                    acc[p] += w0*in[p] + w1_*in[p+1] + w2_*in[p+2];
                wp += 3; hp += S2_STR;
            }
            float b = sb[48+co];
            float sum = 0.f;
            #pragma unroll
            for (int u = 0; u < 4; ++u) {
                int v = ul0 + u;
                if (v < V3) {
                    float y = fmaxf(fmaxf(acc[2*u]+b, 0.f), fmaxf(acc[2*u+1]+b, 0.f));
                    sum += y;
                }
            }
            facc[tid] = sum;
        }
        __syncthreads();

        // ---- reduce this unit's partials -> g_part (deterministic) ----
        if (tid < 16) {
            float s = 0.f;
            #pragma unroll
            for (int u = 0; u < 15; ++u) s += facc[tid + 16*u];
            g_part[unit*16 + tid] = s;
        }
        // next iteration's h0 writes are fenced by the A-phase sync
    }
}

// reduce tiles -> per-sequence mean features
__global__ void mean_kernel()
{
    int i = blockIdx.x * blockDim.x + threadIdx.x;   // 0..32767
    if (i >= NSEQ*16) return;
    int n = i >> 4, c = i & 15;
    float s = 0.f;
    #pragma unroll
    for (int t = 0; t < NTILES; ++t) s += g_part[(n*NTILES + t)*16 + c];
    g_feat[i] = s * (1.0f / 513.0f);
}

// Final: feat [B, J*16=128] -> maxpool k=3 -> [B, 42]
__global__ void final_pool(float* __restrict__ out)
{
    int i = blockIdx.x * blockDim.x + threadIdx.x;
    if (i >= 256*42) return;
    int b = i / 42;
    int g = i - b*42;
    float m = -1e30f;
    #pragma unroll
    for (int e3 = 0; e3 < 3; ++e3) {
        int e = 3*g + e3;
        int j = e >> 4;
        int c = e & 15;
        m = fmaxf(m, g_feat[(b*8 + j)*16 + c]);
    }
    out[i] = m;
}

extern "C" void kernel_launch(void* const* d_in, const int* in_sizes, int n_in,
                              void* d_out, int out_size)
{
    (void)in_sizes; (void)n_in; (void)out_size;
    const float* x  = (const float*)d_in[0];
    const float* w1 = (const float*)d_in[1];
    const float* b1 = (const float*)d_in[2];
    const float* w2 = (const float*)d_in[3];
    const float* b2 = (const float*)d_in[4];
    const float* w3 = (const float*)d_in[5];
    const float* b3 = (const float*)d_in[6];
    float* out = (float*)d_out;

    cudaFuncSetAttribute(cnn_main, cudaFuncAttributeMaxDynamicSharedMemorySize, SMEM_BYTES);
    cnn_main<<<GRIDP, 256, SMEM_BYTES>>>(x, w1, b1, w2, b2, w3, b3);
    mean_kernel<<<(NSEQ*16 + 255)/256, 256>>>();
    final_pool<<<42, 256>>>(out);
}

// round 16
// speedup vs baseline: 1.0859x; 1.0859x over previous
#include <cuda_runtime.h>

// Problem constants
#define TT    4096
#define FF    9
#define NSEQ  2048
#define L1    2049
#define L2    1025
#define L3    513

// Tiling: 8 tiles x 61 + 1 tail tile x 25 = 513 exactly.
// V3=61 packs every phase pass exactly: B 8x64=512 (2 passes), C 16x32=512 (2), D 16x16=256 (1).
// Tail tile (25) runs every phase in ONE pass: B 248, C 240, D 112.
#define V3A     61
#define NTILES  9
#define IN_LEN  502             // 8*61+14
#define NLOAD   (IN_LEN*FF)     // 4518
#define NPF     18              // ceil(4518/256)
#define IN_STR  516             // reads <=513 (zero pad)
#define S1_STR  260             // writes 256, reads <=257; mult of 4 (float4 rows), mod32=4 -> order-8 banks
#define S2_STR  132             // writes 128, reads <=129; mult of 4, mod32=4 -> order-8 banks
#define W2_STR  49
#define W3_STR  97

#define OFF_S1   (9*IN_STR)                 // 4644
#define OFF_S2   (OFF_S1 + 16*S1_STR)       // 8804
#define OFF_W1   (OFF_S2 + 32*S2_STR)       // 13028
#define OFF_W2   (OFF_W1 + 432)             // 13460
#define OFF_W3   (OFF_W2 + 32*W2_STR)       // 15028
#define OFF_SB   (OFF_W3 + 16*W3_STR)       // 16580
#define OFF_FACC (OFF_SB + 64)              // 16644
#define SM_FLOATS (OFF_FACC + 256)          // 16900
#define SMEM_BYTES (SM_FLOATS * 4)

__device__ float g_feat[NSEQ * 16];

__global__ __launch_bounds__(256) void cnn_main(
    const float* __restrict__ x,
    const float* __restrict__ w1, const float* __restrict__ b1,
    const float* __restrict__ w2, const float* __restrict__ b2,
    const float* __restrict__ w3, const float* __restrict__ b3)
{
    extern __shared__ float sm[];
    float* h0  = sm;                  // [9][IN_STR]
    float* s1  = sm + OFF_S1;         // [16][S1_STR]
    float* s2  = sm + OFF_S2;         // [32][S2_STR]
    float* sw1 = sm + OFF_W1;
    float* sw2 = sm + OFF_W2;
    float* sw3 = sm + OFF_W3;
    float* sb  = sm + OFF_SB;
    float* facc= sm + OFF_FACC;

    const int tid = threadIdx.x;
    const int n   = blockIdx.x;
    const float* xin = x + (size_t)n * (TT * FF);

    // per-thread (tl, ci) start for the strided load/store walk (stride 256 = 28*9+4)
    const int tl0 = tid / 9;
    const int ci0 = tid - 9 * tl0;

    // Zero all smem once: persistent zero padding.
    for (int i = tid; i < SM_FLOATS; i += 256) sm[i] = 0.f;
    __syncthreads();

    for (int i = tid; i < 16*27; i += 256) sw1[i] = w1[i];
    for (int i = tid; i < 32*48; i += 256) sw2[(i/48)*W2_STR + (i%48)] = w2[i];
    for (int i = tid; i < 16*96; i += 256) sw3[(i/96)*W3_STR + (i%96)] = w3[i];
    if (tid < 16)      sb[tid] = b1[tid];
    else if (tid < 48) sb[tid] = b2[tid-16];
    else if (tid < 64) sb[tid] = b3[tid-48];
    __syncthreads();

    // ---- initial prefetch of tile 0 into registers ----
    float pf[NPF];
    {
        const int tb = -14;
        int tl = tl0, ci = ci0;
        #pragma unroll
        for (int it = 0; it < NPF; ++it) {
            int idx = tid + (it << 8);
            int t   = tb + tl;
            float v = 0.f;
            if (idx < NLOAD && (unsigned)t < (unsigned)TT) v = xin[t*FF + ci];
            pf[it] = v;
            ci += 4; tl += 28; if (ci >= 9) { ci -= 9; ++tl; }
        }
    }

    for (int tile = 0; tile < NTILES; ++tile) {
        const bool full = (tile < 8);
        const int V3t   = full ? V3A : 25;
        const int NBt   = full ? 512 : 248;   // 8 * (64 | 31) quads
        const int NCt   = full ? 512 : 240;   // 16 * (32 | 15) quads
        const int NDt   = full ? 256 : 112;   // 16 * (16 | 7) ug
        const int va    = tile * V3A;
        const int u1b   = 4*va - 6;
        const int u2b   = 2*va - 2;

        // ---- Phase A: store prefetched regs -> h0 (pure STS) ----
        {
            int tl = tl0, ci = ci0;
            #pragma unroll
            for (int it = 0; it < NPF; ++it) {
                int idx = tid + (it << 8);
                if (idx < NLOAD) h0[ci*IN_STR + tl] = pf[it];
                ci += 4; tl += 28; if (ci >= 9) { ci -= 9; ++tl; }
            }
        }
        __syncthreads();

        // ---- issue next tile's LDGs now; latency hidden by B/C/D ----
        if (tile + 1 < NTILES) {
            const int tb = 8*((tile+1)*V3A) - 14;
            int tl = tl0, ci = ci0;
            #pragma unroll
            for (int it = 0; it < NPF; ++it) {
                int idx = tid + (it << 8);
                int t   = tb + tl;
                float v = 0.f;
                if (idx < NLOAD && (unsigned)t < (unsigned)TT) v = xin[t*FF + ci];
                pf[it] = v;
                ci += 4; tl += 28; if (ci >= 9) { ci -= 9; ++tl; }
            }
        }

        // ---- Phase B: stage1 conv(9->16,k3,p2) + relu + pool2 ----
        #pragma unroll
        for (int it = 0; it < 2; ++it) {
            int item = tid + it*256;
            if (item < NBt) {
                int cog = item & 7;
                int ug  = item >> 3;
                int co0 = cog * 2;
                int ul0 = ug * 4;
                float acc0[8], acc1[8];
                #pragma unroll
                for (int p = 0; p < 8; ++p) { acc0[p]=0.f; acc1[p]=0.f; }
                const float* wpa = sw1 + co0*27;
                const float* wpb = wpa + 27;
                const float* hp  = h0 + 2*ul0;
                #pragma unroll
                for (int ci = 0; ci < 9; ++ci) {
                    float in[10];
                    #pragma unroll
                    for (int j = 0; j < 10; ++j) in[j] = hp[j];
                    float wa0=wpa[0], wa1=wpa[1], wa2=wpa[2];
                    float wb0=wpb[0], wb1=wpb[1], wb2=wpb[2];
                    #pragma unroll
                    for (int p = 0; p < 8; ++p) {
                        acc0[p] += wa0*in[p] + wa1*in[p+1] + wa2*in[p+2];
                        acc1[p] += wb0*in[p] + wb1*in[p+1] + wb2*in[p+2];
                    }
                    wpa += 3; wpb += 3; hp += IN_STR;
                }
                float ba = sb[co0], bb = sb[co0+1];
                float4 r0, r1;
                float* pr0 = (float*)&r0;
                float* pr1 = (float*)&r1;
                #pragma unroll
                for (int u = 0; u < 4; ++u) {
                    int ug1 = u1b + ul0 + u;
                    bool valid = (ug1 >= 0) && (ug1 < L1);
                    float v0 = fmaxf(fmaxf(acc0[2*u]+ba, 0.f), fmaxf(acc0[2*u+1]+ba, 0.f));
                    float v1 = fmaxf(fmaxf(acc1[2*u]+bb, 0.f), fmaxf(acc1[2*u+1]+bb, 0.f));
                    pr0[u] = valid ? v0 : 0.f;
                    pr1[u] = valid ? v1 : 0.f;
                }
                *(float4*)(s1 +  co0   *S1_STR + ul0) = r0;
                *(float4*)(s1 + (co0+1)*S1_STR + ul0) = r1;
            }
        }
        __syncthreads();

        // ---- Phase C: stage2 conv(16->32,k3,p2) + relu + pool2 ----
        #pragma unroll
        for (int it = 0; it < 2; ++it) {
            int item = tid + it*256;
            if (item < NCt) {
                int cog = item & 15;
                int ug  = item >> 4;
                int co0 = cog * 2;
                int ul0 = ug * 4;
                float acc0[8], acc1[8];
                #pragma unroll
                for (int p = 0; p < 8; ++p) { acc0[p]=0.f; acc1[p]=0.f; }
                const float* wpa = sw2 + co0*W2_STR;
                const float* wpb = wpa + W2_STR;
                const float* hp  = s1 + 2*ul0;
                #pragma unroll 4
                for (int ci = 0; ci < 16; ++ci) {
                    float in[10];
                    #pragma unroll
                    for (int j = 0; j < 10; ++j) in[j] = hp[j];
                    float wa0=wpa[0], wa1=wpa[1], wa2=wpa[2];
                    float wb0=wpb[0], wb1=wpb[1], wb2=wpb[2];
                    #pragma unroll
                    for (int p = 0; p < 8; ++p) {
                        acc0[p] += wa0*in[p] + wa1*in[p+1] + wa2*in[p+2];
                        acc1[p] += wb0*in[p] + wb1*in[p+1] + wb2*in[p+2];
                    }
                    wpa += 3; wpb += 3; hp += S1_STR;
                }
                float ba = sb[16+co0], bb = sb[16+co0+1];
                float4 r0, r1;
                float* pr0 = (float*)&r0;
                float* pr1 = (float*)&r1;
                #pragma unroll
                for (int u = 0; u < 4; ++u) {
                    int ug2 = u2b + ul0 + u;
                    bool valid = (ug2 >= 0) && (ug2 < L2);
                    float v0 = fmaxf(fmaxf(acc0[2*u]+ba, 0.f), fmaxf(acc0[2*u+1]+ba, 0.f));
                    float v1 = fmaxf(fmaxf(acc1[2*u]+bb, 0.f), fmaxf(acc1[2*u+1]+bb, 0.f));
                    pr0[u] = valid ? v0 : 0.f;
                    pr1[u] = valid ? v1 : 0.f;
                }
                *(float4*)(s2 +  co0   *S2_STR + ul0) = r0;
                *(float4*)(s2 + (co0+1)*S2_STR + ul0) = r1;
            }
        }
        __syncthreads();

        // ---- Phase D: stage3 conv(32->16,k3,p2) + relu + pool2 + mean-acc ----
        if (tid < NDt) {
            int co  = tid & 15;
            int ug  = tid >> 4;
            int ul0 = ug * 4;
            float acc[8];
            #pragma unroll
            for (int p = 0; p < 8; ++p) acc[p] = 0.f;
            const float* wp = sw3 + co*W3_STR;
            const float* hp = s2 + 2*ul0;
            #pragma unroll 4
            for (int ci = 0; ci < 32; ++ci) {
                float in[10];
                #pragma unroll
                for (int j = 0; j < 10; ++j) in[j] = hp[j];
                float w0=wp[0], w1_=wp[1], w2_=wp[2];
                #pragma unroll
                for (int p = 0; p < 8; ++p)
                    acc[p] += w0*in[p] + w1_*in[p+1] + w2_*in[p+2];
                wp += 3; hp += S2_STR;
            }
            float b = sb[48+co];
            float sum = 0.f;
            #pragma unroll
            for (int u = 0; u < 4; ++u) {
                int v = ul0 + u;                // local pooled index
                if (v < V3t) {
                    float y = fmaxf(fmaxf(acc[2*u]+b, 0.f), fmaxf(acc[2*u+1]+b, 0.f));
                    sum += y;
                }
            }
            facc[tid] += sum;
        }
        __syncthreads();
    }

    // ---- mean over L3=513 positions ----
    if (tid < 16) {
        float s = 0.f;
        #pragma unroll
        for (int u = 0; u < 16; ++u) s += facc[tid + 16*u];
        g_feat[n*16 + tid] = s * (1.0f / 513.0f);
    }
}

// Final: feat [B, J*16=128] -> maxpool k=3 -> [B, 42]
__global__ void final_pool(float* __restrict__ out)
{
    int i = blockIdx.x * blockDim.x + threadIdx.x;
    if (i >= 256*42) return;
    int b = i / 42;
    int g = i - b*42;
    float m = -1e30f;
    #pragma unroll
    for (int e3 = 0; e3 < 3; ++e3) {
        int e = 3*g + e3;
        int j = e >> 4;
        int c = e & 15;
        m = fmaxf(m, g_feat[(b*8 + j)*16 + c]);
    }
    out[i] = m;
}

extern "C" void kernel_launch(void* const* d_in, const int* in_sizes, int n_in,
                              void* d_out, int out_size)
{
    (void)in_sizes; (void)n_in; (void)out_size;
    const float* x  = (const float*)d_in[0];
    const float* w1 = (const float*)d_in[1];
    const float* b1 = (const float*)d_in[2];
    const float* w2 = (const float*)d_in[3];
    const float* b2 = (const float*)d_in[4];
    const float* w3 = (const float*)d_in[5];
    const float* b3 = (const float*)d_in[6];
    float* out = (float*)d_out;

    cudaFuncSetAttribute(cnn_main, cudaFuncAttributeMaxDynamicSharedMemorySize, SMEM_BYTES);
    cnn_main<<<NSEQ, 256, SMEM_BYTES>>>(x, w1, b1, w2, b2, w3, b3);
    final_pool<<<42, 256>>>(out);
}